// round 5
// baseline (speedup 1.0000x reference)
#include <cuda_runtime.h>
#include <cuda_bf16.h>

#define SQRT5F 2.23606797749978969f

// Output: out[i][a][j][b].
// k[i,a,j,b] = c^2 * ( A(i,j)*inv_l2[a]*delta(a,b) - 5*fr(i,j)*D[i,j,a]*D[i,j,b] )
//
// Block = 256 threads = 128 (i,j) pairs: one i row, 128 contiguous j.
// X2 tile (4KB) staged in smem via one coalesced LDG.128/thread.
// il2 / x1 / c2 computed once per block into smem (kills 8 RCP MUFUs/thread).
// Two lanes per pair (h = b-half), so each STG.128's lanes are contiguous at
// 16B stride -> full-line L1 wavefronts (store wavefront floor).

__global__ __launch_bounds__(256, 8)
void deriv2_matern52_kernel(const float* __restrict__ X1,
                            const float* __restrict__ X2,
                            const float* __restrict__ c_ptr,
                            const float* __restrict__ l,
                            float* __restrict__ out,
                            int n, int m, int tiles_per_row) {
    constexpr int D = 8;
    constexpr int PAIRS = 128;           // pairs per block

    __shared__ float s_x2[PAIRS * D];    // 4KB
    __shared__ float s_x1[D];
    __shared__ float s_il2[D];
    __shared__ float s_c2;

    const int tile = blockIdx.x;
    const int i  = tile / tiles_per_row;
    const int j0 = (tile - i * tiles_per_row) * PAIRS;
    const int tid = threadIdx.x;

    // Stage X2 tile: 128 rows * 8 floats = 256 float4. One LDG.128 per thread,
    // fully coalesced.
    {
        const int elem = j0 * (D / 4) + tid;        // float4 index into X2
        const int limit = m * (D / 4);
        float4 v = (elem < limit)
                 ? reinterpret_cast<const float4*>(X2)[elem]
                 : make_float4(0.f, 0.f, 0.f, 0.f);
        reinterpret_cast<float4*>(s_x2)[tid] = v;
    }
    if (tid < D) {
        s_x1[tid] = X1[(size_t)i * D + tid];
        float lv = l[tid];
        s_il2[tid] = 1.0f / (lv * lv);
    }
    if (tid == 0) {
        float cv = *c_ptr;
        s_c2 = cv * cv;
    }
    __syncthreads();

    const int p = tid >> 1;              // local pair index
    const int h = tid & 1;               // b-half
    const int j = j0 + p;
    if (j >= m) return;

    float x1r[D], il2[D];
#pragma unroll
    for (int k = 0; k < D; ++k) { x1r[k] = s_x1[k]; il2[k] = s_il2[k]; }
    const float c2 = s_c2;

    // X2 row from smem: two LDS.128 (lane pairs broadcast).
    const float4* x2v = reinterpret_cast<const float4*>(s_x2 + p * D);
    float4 x2a = x2v[0];
    float4 x2b = x2v[1];
    float x2r[D] = {x2a.x, x2a.y, x2a.z, x2a.w, x2b.x, x2b.y, x2b.z, x2b.w};

    float Dv[D];
    float r2 = 0.0f;
#pragma unroll
    for (int k = 0; k < D; ++k) {
        float dx = x1r[k] - x2r[k];
        Dv[k] = dx * il2[k];
        r2 = fmaf(dx, Dv[k], r2);
    }

    const float r  = sqrtf(r2);
    const float fr = (5.0f / 3.0f) * __expf(-SQRT5F * r);
    const float A  = fr * fmaf(SQRT5F, r, 1.0f);

    const float Ac   = A * c2;
    const float m5fc = -5.0f * fr * c2;

    // This lane's b-half of Dv (selects, no dynamic reg indexing).
    float Dh[4];
#pragma unroll
    for (int b4 = 0; b4 < 4; ++b4) Dh[b4] = h ? Dv[b4 + 4] : Dv[b4];
    const int bbase = h << 2;

    float* base = out + (((size_t)i * D * m + j) * D + bbase);
    const size_t a_stride = (size_t)m * D;

#pragma unroll
    for (int a = 0; a < D; ++a) {
        const float fa = m5fc * Dv[a];
        float v0 = fa * Dh[0];
        float v1 = fa * Dh[1];
        float v2 = fa * Dh[2];
        float v3 = fa * Dh[3];
        const float diag = Ac * il2[a];
        if (bbase + 0 == a) v0 += diag;
        if (bbase + 1 == a) v1 += diag;
        if (bbase + 2 == a) v2 += diag;
        if (bbase + 3 == a) v3 += diag;
        // Streaming store: write-once 256MB output, keep out of L2.
        __stcs(reinterpret_cast<float4*>(base + a * a_stride),
               make_float4(v0, v1, v2, v3));
    }
}

extern "C" void kernel_launch(void* const* d_in, const int* in_sizes, int n_in,
                              void* d_out, int out_size) {
    // Expected metadata order: X1 [n*d], X2 [m*d], c [1], l [d].
    const float* X1 = (const float*)d_in[0];
    const float* X2 = (const float*)d_in[1];
    const float* c;
    const float* l;
    int d;
    if (in_sizes[2] == 1) {
        c = (const float*)d_in[2];
        l = (const float*)d_in[3];
        d = in_sizes[3];
    } else {
        l = (const float*)d_in[2];
        c = (const float*)d_in[3];
        d = in_sizes[2];
    }
    float* out = (float*)d_out;

    const int n = in_sizes[0] / d;      // 1024
    const int m = in_sizes[1] / d;      // 1024

    const int PAIRS = 128;
    const int tiles_per_row = (m + PAIRS - 1) / PAIRS;
    const int blocks = n * tiles_per_row;
    deriv2_matern52_kernel<<<blocks, 256>>>(X1, X2, c, l, out, n, m,
                                            tiles_per_row);
}